// round 12
// baseline (speedup 1.0000x reference)
#include <cuda_runtime.h>
#include <cuda_fp16.h>
#include <math.h>

#define BB   4
#define SS   1024
#define HIDC 768
#define HH   6
#define DD   64
#define AHC  384
#define KSC  9
#define PADC 4
#define OW   768   // output width = 2*AH
#define CKN  54    // H*KS
#define CKZ  6     // split-K factor for ck GEMM

typedef unsigned long long ull;

// ---------------- f32x2 packed helpers ----------------
__device__ __forceinline__ void ffma2(ull& d, ull a, ull b) {
    asm("fma.rn.f32x2 %0, %1, %2, %3;" : "=l"(d) : "l"(a), "l"(b), "l"(d));
}
__device__ __forceinline__ void unpack2(float& lo, float& hi, ull v) {
    asm("mov.b64 {%0, %1}, %2;" : "=f"(lo), "=f"(hi) : "l"(v));
}

// ---------------- scratch (device globals: no allocations allowed) ----------------
__device__ float g_mq [BB*SS*AHC];
__device__ float g_mk [BB*SS*AHC];
__device__ float g_mv [BB*SS*AHC];
__device__ float g_co [BB*SS*AHC];
__device__ float g_mkc[BB*SS*AHC];
__device__ float g_dwt[BB*SS*HIDC];
__device__ float g_ck [BB*SS*CKN];
__device__ float g_ckp[CKZ*BB*SS*CKN];   // split-K partials for ck logits
__device__ float g_tdsm[BB*SS];
__device__ float  g_sc [(size_t)BB*HH*SS*SS];   // scores (100 MB)
__device__ __half g_pr [(size_t)BB*HH*SS*SS];   // probs fp16 (50 MB)

// ---------------- GEMM core: C[M,N] = scale*(A@B) (+bias), 128x64 tile, f32x2 ----------------
// m-PAIRED accumulators: acc[mp][nn] = {C[m_even][n], C[m_odd][n]}.
// A staged normally (a-pairs = free register aliases of LDS.128);
// B staged DUPLICATED (Bs[k][2n]=Bs[k][2n+1]=B[n]) -> zero packing MOVs.
// BT=false: B is [K,N]-style row-major (row stride ldb); BT=true: C = A @ B^T.
// AHALF: A is fp16 (probs); converted during staging.
template<bool BT, bool BIAS, bool NGUARD, bool AMUL, bool AHALF>
__device__ __forceinline__ void gemm_core(const float* __restrict__ A,
                                          const float* __restrict__ A2,
                                          const float* __restrict__ Bm,
                                          const float* __restrict__ bias,
                                          float* __restrict__ C,
                                          int N, int m0, int n0,
                                          int kBeg, int kEnd,
                                          int lda, int ldb, int ldc, float scale)
{
    __shared__ float As[16][128];
    __shared__ float Bs[16][128];   // duplicated pairs
    const int tid = threadIdx.x;
    const int ty = tid >> 4, tx = tid & 15;
    const int lr = tid >> 1, lk = (tid & 1) * 8;

    ull acc[4][4];
#pragma unroll
    for (int mp = 0; mp < 4; mp++)
#pragma unroll
        for (int nn = 0; nn < 4; nn++) acc[mp][nn] = 0ull;

    for (int k0 = kBeg; k0 < kEnd; k0 += 16) {
        // ---- stage A (128 x 16) ----
        {
            float av[8];
            if (!AHALF) {
                const float* ap = A + (size_t)(m0 + lr) * lda + k0 + lk;
                float4 a0 = *(const float4*)(ap);
                float4 a1 = *(const float4*)(ap + 4);
                if (AMUL) {
                    const float* a2p = A2 + (size_t)(m0 + lr) * lda + k0 + lk;
                    float4 m0v = *(const float4*)(a2p);
                    float4 m1v = *(const float4*)(a2p + 4);
                    a0.x *= m0v.x; a0.y *= m0v.y; a0.z *= m0v.z; a0.w *= m0v.w;
                    a1.x *= m1v.x; a1.y *= m1v.y; a1.z *= m1v.z; a1.w *= m1v.w;
                }
                av[0] = a0.x; av[1] = a0.y; av[2] = a0.z; av[3] = a0.w;
                av[4] = a1.x; av[5] = a1.y; av[6] = a1.z; av[7] = a1.w;
            } else {
                const __half* ah = (const __half*)A + (size_t)(m0 + lr) * lda + k0 + lk;
                uint4 hv = *(const uint4*)ah;   // 8 halves
                float2 f0 = __half22float2(*(const __half2*)&hv.x);
                float2 f1 = __half22float2(*(const __half2*)&hv.y);
                float2 f2 = __half22float2(*(const __half2*)&hv.z);
                float2 f3 = __half22float2(*(const __half2*)&hv.w);
                av[0] = f0.x; av[1] = f0.y; av[2] = f1.x; av[3] = f1.y;
                av[4] = f2.x; av[5] = f2.y; av[6] = f3.x; av[7] = f3.y;
            }
#pragma unroll
            for (int i = 0; i < 8; i++) As[lk + i][lr] = av[i];
        }
        // ---- stage B (16 x 64), duplicated ----
        if (!BT) {
            int bk = tid >> 4, bn = (tid & 15) * 4;
            if (!NGUARD) {
                float4 bv = *(const float4*)(Bm + (size_t)(k0 + bk) * ldb + n0 + bn);
                *(float4*)&Bs[bk][2 * bn]     = make_float4(bv.x, bv.x, bv.y, bv.y);
                *(float4*)&Bs[bk][2 * bn + 4] = make_float4(bv.z, bv.z, bv.w, bv.w);
            } else {
#pragma unroll
                for (int j = 0; j < 4; j++) {
                    int n = n0 + bn + j;
                    float v = (n < N) ? Bm[(size_t)(k0 + bk) * ldb + n] : 0.f;
                    *(float2*)&Bs[bk][2 * (bn + j)] = make_float2(v, v);
                }
            }
        } else {
            int bn = tid >> 2, bkk = (tid & 3) * 4;
            float4 bv = *(const float4*)(Bm + (size_t)(n0 + bn) * ldb + k0 + bkk);
            *(float2*)&Bs[bkk + 0][2 * bn] = make_float2(bv.x, bv.x);
            *(float2*)&Bs[bkk + 1][2 * bn] = make_float2(bv.y, bv.y);
            *(float2*)&Bs[bkk + 2][2 * bn] = make_float2(bv.z, bv.z);
            *(float2*)&Bs[bkk + 3][2 * bn] = make_float2(bv.w, bv.w);
        }
        __syncthreads();
#pragma unroll
        for (int k = 0; k < 16; k++) {
            const ull* ap_ = (const ull*)&As[k][ty * 8];
            ull a0 = ap_[0], a1 = ap_[1], a2 = ap_[2], a3 = ap_[3];
            const ull* bp_ = (const ull*)&Bs[k][tx * 8];
            ull b0 = bp_[0], b1 = bp_[1], b2 = bp_[2], b3 = bp_[3];
            ffma2(acc[0][0], a0, b0); ffma2(acc[0][1], a0, b1);
            ffma2(acc[0][2], a0, b2); ffma2(acc[0][3], a0, b3);
            ffma2(acc[1][0], a1, b0); ffma2(acc[1][1], a1, b1);
            ffma2(acc[1][2], a1, b2); ffma2(acc[1][3], a1, b3);
            ffma2(acc[2][0], a2, b0); ffma2(acc[2][1], a2, b1);
            ffma2(acc[2][2], a2, b2); ffma2(acc[2][3], a2, b3);
            ffma2(acc[3][0], a3, b0); ffma2(acc[3][1], a3, b1);
            ffma2(acc[3][2], a3, b2); ffma2(acc[3][3], a3, b3);
        }
        __syncthreads();
    }
#pragma unroll
    for (int mp = 0; mp < 4; mp++) {
        int me = m0 + ty * 8 + 2 * mp;
#pragma unroll
        for (int nn = 0; nn < 4; nn++) {
            float lo, hi; unpack2(lo, hi, acc[mp][nn]);
            int n = n0 + tx * 4 + nn;
            if (!NGUARD || n < N) {
                float ve = lo * scale, vo = hi * scale;
                if (BIAS) { float bb = bias[n]; ve += bb; vo += bb; }
                C[(size_t)me * ldc + n] = ve;
                C[(size_t)(me + 1) * ldc + n] = vo;
            }
        }
    }
}

// fused 4-way projection GEMM: z selects (A, B, bias, C)
__global__ void __launch_bounds__(256) gemm_fused(const float* __restrict__ Q,
                                                  const float* __restrict__ Kin,
                                                  const float* __restrict__ V,
                                                  const float* __restrict__ Wq,
                                                  const float* __restrict__ Wk,
                                                  const float* __restrict__ Wv,
                                                  const float* __restrict__ coW,
                                                  const float* __restrict__ cob,
                                                  float* __restrict__ mq,
                                                  float* __restrict__ mk,
                                                  float* __restrict__ mv,
                                                  float* __restrict__ co)
{
    int m0 = blockIdx.x * 128, n0 = blockIdx.y * 64;
    switch (blockIdx.z) {
    case 0: gemm_core<false,false,false,false,false>(Q,   nullptr, Wq,  nullptr, mq, AHC, m0, n0, 0, HIDC, HIDC, AHC, AHC, 1.f); break;
    case 1: gemm_core<false,false,false,false,false>(Kin, nullptr, Wk,  nullptr, mk, AHC, m0, n0, 0, HIDC, HIDC, AHC, AHC, 1.f); break;
    case 2: gemm_core<false,false,false,false,false>(V,   nullptr, Wv,  nullptr, mv, AHC, m0, n0, 0, HIDC, HIDC, AHC, AHC, 1.f); break;
    default:gemm_core<false,true, false,false,false>(V,   nullptr, coW, cob,     co, AHC, m0, n0, 0, HIDC, HIDC, AHC, AHC, 1.f); break;
    }
}

// pointwise conv GEMM: mkc = dwt @ pw_w^T + sep_b
__global__ void __launch_bounds__(256) gemm_pw(const float* __restrict__ dwt,
                                               const float* __restrict__ pw,
                                               const float* __restrict__ sb,
                                               float* __restrict__ mkc)
{
    gemm_core<true, true, false, false, false>(dwt, nullptr, pw, sb, mkc,
                                               AHC, blockIdx.x * 128, blockIdx.y * 64,
                                               0, HIDC, HIDC, HIDC, AHC, 1.f);
}

// ck logits GEMM, split-K x CKZ
__global__ void __launch_bounds__(256) gemm_ck(const float* __restrict__ mkc,
                                               const float* __restrict__ mq,
                                               const float* __restrict__ ckW,
                                               const float* __restrict__ ckb,
                                               float* __restrict__ ckp)
{
    int z = blockIdx.z;
    const int KS_ = AHC / CKZ;   // 64
    float* Cz = ckp + (size_t)z * (BB * SS * CKN);
    if (z == 0)
        gemm_core<false, true,  true, true, false>(mkc, mq, ckW, ckb, Cz,
                                                   CKN, blockIdx.x * 128, 0, 0, KS_,
                                                   AHC, CKN, CKN, 1.f);
    else
        gemm_core<false, false, true, true, false>(mkc, mq, ckW, nullptr, Cz,
                                                   CKN, blockIdx.x * 128, 0, z * KS_, z * KS_ + KS_,
                                                   AHC, CKN, CKN, 1.f);
}

// QK GEMM: scores[b,h][i][j] = (mq_i . mk_j) / 8
__global__ void __launch_bounds__(256) gemm_qk(const float* __restrict__ mq,
                                               const float* __restrict__ mk,
                                               float* __restrict__ sc)
{
    int z = blockIdx.z;             // b*HH + h
    int b = z / HH, h = z % HH;
    const float* Aq = mq + (size_t)(b * SS) * AHC + h * DD;
    const float* Bk = mk + (size_t)(b * SS) * AHC + h * DD;
    float* Cz = sc + (size_t)z * SS * SS;
    gemm_core<true, false, false, false, false>(Aq, nullptr, Bk, nullptr, Cz,
                                                SS, blockIdx.x * 128, blockIdx.y * 64,
                                                0, DD, AHC, AHC, SS, 0.125f);
}

// PV GEMM: out[b][i][h*DD+d] = sum_j probs_fp16[i][j] * mv[j][d]
__global__ void __launch_bounds__(256) gemm_pv(const __half* __restrict__ pr,
                                               const float* __restrict__ mv,
                                               float* __restrict__ out)
{
    int z = blockIdx.z;
    int b = z / HH, h = z % HH;
    const __half* Ap = pr + (size_t)z * SS * SS;
    const float* Bv = mv + (size_t)(b * SS) * AHC + h * DD;
    float* Cz = out + (size_t)(b * SS) * OW + h * DD;
    gemm_core<false, false, false, false, true>((const float*)Ap, nullptr, Bv, nullptr, Cz,
                                                64, blockIdx.x * 128, 0,
                                                0, SS, SS, AHC, OW, 1.f);
}

// ---------------- softmax / distance-decay: fp32 scores -> fp16 probs ----------------
// grid (S/8, H, B); 8 warps x 1 row. Row staged smem-pitched (j + (j>>5)).
__global__ void __launch_bounds__(256) softmax_kernel(const int* __restrict__ mask,
                                                      const float* __restrict__ gammas,
                                                      const float* __restrict__ sc,
                                                      __half* __restrict__ pr)
{
    __shared__ float srows[8 * 1056];
    __shared__ float tdsT[1024];
    __shared__ unsigned mbits[32];

    const int tid  = threadIdx.x;
    const int w    = tid >> 5, lane = tid & 31;
    const int h    = blockIdx.y;
    const int b    = blockIdx.z;
    const int i    = blockIdx.x * 8 + w;

    for (int base = tid; base < SS; base += 256) {
        int mv = mask[b * SS + base];
        unsigned bal = __ballot_sync(0xffffffffu, mv != 0);
        if (lane == 0) mbits[base >> 5] = bal;
    }
    for (int j = tid; j < SS; j += 256)
        tdsT[((j & 31) << 5) | (j >> 5)] = g_tdsm[b * SS + j];
    __syncthreads();

    float gv = gammas[h];
    float gamma = -(gv > 20.f ? gv : log1pf(expf(gv)));   // -softplus

    float* srow = srows + w * 1056;
    const float* grow = sc + ((size_t)((b * HH + h)) * SS + i) * SS;
    __half* prow = pr + ((size_t)((b * HH + h)) * SS + i) * SS;

    // stage row: coalesced LDG.128 -> pitched smem (conflict-free)
#pragma unroll
    for (int t = 0; t < 8; t++) {
        float4 v = *(const float4*)(grow + t * 128 + lane * 4);
        int a = t * 132 + lane * 4 + (lane >> 3);
        srow[a] = v.x; srow[a + 1] = v.y; srow[a + 2] = v.z; srow[a + 3] = v.w;
    }
    __syncwarp();

    const unsigned mrow = mbits[lane];
    float sv[32];
#pragma unroll
    for (int c = 0; c < 32; c++) sv[c] = srow[lane * 33 + c];

    // pass 1: masked max
    float m1 = -3e38f;
#pragma unroll
    for (int c = 0; c < 32; c++)
        if ((mrow >> c) & 1) m1 = fmaxf(m1, sv[c]);
#pragma unroll
    for (int o = 16; o; o >>= 1) m1 = fmaxf(m1, __shfl_xor_sync(0xffffffffu, m1, o));

    // pass 2: p ~ exp * mask, inclusive cumsum
    float cuml[32];
    float run = 0.f;
#pragma unroll
    for (int c = 0; c < 32; c++) {
        float p = ((mrow >> c) & 1) ? expf(sv[c] - m1) : 0.f;
        run += p;
        cuml[c] = run;
    }
    float v = run;
#pragma unroll
    for (int o = 1; o < 32; o <<= 1) {
        float t = __shfl_up_sync(0xffffffffu, v, o);
        if (lane >= o) v += t;
    }
    float total = __shfl_sync(0xffffffffu, v, 31);
    float off = v - run;
    float invtot = 1.f / fmaxf(total, 1e-30f);

    // pass 3: total_effect, modified scores, max
    float m2 = -3e38f;
#pragma unroll
    for (int c = 0; c < 32; c++) {
        int j = lane * 32 + c;
        float s2;
        if ((mrow >> c) & 1) {
            float cum = cuml[c] + off;
            float pos = fabsf((float)(j - i));
            float rem = (total - cum) * invtot;
            float ds = sqrtf(fmaxf(rem * pos, 0.f));
            float te = expf(gamma * ds);
            te = fminf(fmaxf(te, 1e-5f), 1e5f);
            if (j < i) te -= tdsT[(c << 5) | lane];
            s2 = sv[c] * te;
        } else {
            s2 = -1e8f;
        }
        sv[c] = s2;
        m2 = fmaxf(m2, s2);
    }
#pragma unroll
    for (int o = 16; o; o >>= 1) m2 = fmaxf(m2, __shfl_xor_sync(0xffffffffu, m2, o));

    // pass 4: exp + sum, normalize, stage back
    float sum2 = 0.f;
#pragma unroll
    for (int c = 0; c < 32; c++) {
        float e = expf(sv[c] - m2);
        sv[c] = e;
        sum2 += e;
    }
#pragma unroll
    for (int o = 16; o; o >>= 1) sum2 += __shfl_xor_sync(0xffffffffu, sum2, o);
    float invs = 1.f / sum2;
#pragma unroll
    for (int c = 0; c < 32; c++) srow[lane * 33 + c] = sv[c] * invs;
    __syncwarp();

    // write back coalesced as fp16
#pragma unroll
    for (int t = 0; t < 8; t++) {
        int a = t * 132 + lane * 4 + (lane >> 3);
        __half2 h0 = __floats2half2_rn(srow[a], srow[a + 1]);
        __half2 h1 = __floats2half2_rn(srow[a + 2], srow[a + 3]);
        unsigned u0 = *(unsigned*)&h0, u1 = *(unsigned*)&h1;
        *(uint2*)(prow + t * 128 + lane * 4) = make_uint2(u0, u1);
    }
}

// ck: sum CKZ partials, softmax over KS=9, write g_ck
__global__ void __launch_bounds__(256) cksm_kernel()
{
    int row = blockIdx.x * 256 + threadIdx.x;     // BB*SS*HH rows
    if (row >= BB * SS * HH) return;
    const size_t R = (size_t)BB * SS * CKN;
    const float* p0 = g_ckp + (size_t)row * KSC;
    float v[KSC];
    float m = -3e38f;
#pragma unroll
    for (int k = 0; k < KSC; k++) {
        float s = 0.f;
#pragma unroll
        for (int z = 0; z < CKZ; z++) s += p0[z * R + k];
        v[k] = s;
        m = fmaxf(m, s);
    }
    float sum = 0.f;
#pragma unroll
    for (int k = 0; k < KSC; k++) { v[k] = expf(v[k] - m); sum += v[k]; }
    float invs = 1.f / sum;
    float* o = g_ck + (size_t)row * KSC;
#pragma unroll
    for (int k = 0; k < KSC; k++) o[k] = v[k] * invs;
}

// ---------------- depthwise conv, smem-tiled (16 s x 256 ch per block) ----------------
__global__ void __launch_bounds__(256) dw_kernel(const float* __restrict__ Kin,
                                                 const float* __restrict__ dw_w)
{
    __shared__ float smk[24][256];
    __shared__ float wsm[KSC][256];
    const int tid = threadIdx.x;
    const int c0  = blockIdx.x * 256;
    const int s0  = blockIdx.y * 16;
    const int b   = blockIdx.z;

    // stage 24 input rows (s0-4 .. s0+19), zero-padded
#pragma unroll
    for (int r = 0; r < 24; r++) {
        int sr = s0 + r - PADC;
        smk[r][tid] = (sr >= 0 && sr < SS)
            ? Kin[(size_t)(b * SS + sr) * HIDC + c0 + tid] : 0.f;
    }
    // stage weights
    for (int idx = tid; idx < 256 * KSC; idx += 256) {
        int cl = idx / KSC, k = idx % KSC;
        wsm[k][cl] = dw_w[(c0 + cl) * KSC + k];
    }
    __syncthreads();

#pragma unroll
    for (int sl = 0; sl < 16; sl++) {
        float acc = 0.f;
#pragma unroll
        for (int k = 0; k < KSC; k++)
            acc += smk[sl + k][tid] * wsm[k][tid];
        g_dwt[(size_t)(b * SS + s0 + sl) * HIDC + c0 + tid] = acc;
    }
}

// ---------------- conv_out: sliding-window gather of co weighted by ck ----------------
__global__ void __launch_bounds__(128) conv_out_kernel(float* __restrict__ out)
{
    int bs = blockIdx.x;
    int b = bs >> 10, s = bs & 1023;
    __shared__ float cks[CKN];
    if (threadIdx.x < CKN) cks[threadIdx.x] = g_ck[(size_t)bs * CKN + threadIdx.x];
    __syncthreads();
    for (int a = threadIdx.x; a < AHC; a += 128) {
        int h = a >> 6;
        float acc = 0.f;
#pragma unroll
        for (int k = 0; k < KSC; k++) {
            int sr = s + k - PADC;
            if (sr >= 0 && sr < SS)
                acc += g_co[(size_t)(b * SS + sr) * AHC + a] * cks[h * KSC + k];
        }
        out[(size_t)bs * OW + AHC + a] = acc;
    }
}

// ---------------- td softmax (independent of head and query row) ----------------
__global__ void __launch_bounds__(256) tdsm_kernel(const float* __restrict__ td,
                                                   const int* __restrict__ mask)
{
    __shared__ float red[8];
    __shared__ float bc;
    int b = blockIdx.x, tid = threadIdx.x;
    int wid = tid >> 5, ln = tid & 31;

    float ss = 0.f;
    for (int j = tid; j < SS; j += 256) { float v = td[b * SS + j]; ss += v * v; }
#pragma unroll
    for (int o = 16; o; o >>= 1) ss += __shfl_xor_sync(0xffffffffu, ss, o);
    if (ln == 0) red[wid] = ss;
    __syncthreads();
    if (tid == 0) {
        float t = 0.f;
        for (int k = 0; k < 8; k++) t += red[k];
        bc = 1.f / fmaxf(sqrtf(t), 1e-12f);
    }
    __syncthreads();
    float inv = bc;

    float m = -1e4f;
    for (int j = tid; j < SS; j += 256)
        if (mask[b * SS + j]) m = fmaxf(m, td[b * SS + j] * inv);
#pragma unroll
    for (int o = 16; o; o >>= 1) m = fmaxf(m, __shfl_xor_sync(0xffffffffu, m, o));
    if (ln == 0) red[wid] = m;
    __syncthreads();
    if (tid == 0) {
        float t = -1e4f;
        for (int k = 0; k < 8; k++) t = fmaxf(t, red[k]);
        bc = t;
    }
    __syncthreads();
    float mm = bc;
    __syncthreads();

    float den = 0.f;
    for (int j = tid; j < SS; j += 256)
        if (mask[b * SS + j]) den += expf(td[b * SS + j] * inv - mm);
#pragma unroll
    for (int o = 16; o; o >>= 1) den += __shfl_xor_sync(0xffffffffu, den, o);
    if (ln == 0) red[wid] = den;
    __syncthreads();
    if (tid == 0) {
        float t = 0.f;
        for (int k = 0; k < 8; k++) t += red[k];
        bc = 1.f / t;
    }
    __syncthreads();
    float invden = bc;

    for (int j = tid; j < SS; j += 256) {
        float v = mask[b * SS + j] ? expf(td[b * SS + j] * inv - mm) * invden : 0.f;
        g_tdsm[b * SS + j] = v;
    }
}

// ---------------- launch ----------------
extern "C" void kernel_launch(void* const* d_in, const int* in_sizes, int n_in,
                              void* d_out, int out_size)
{
    const float* Q      = (const float*)d_in[0];
    const float* Kin    = (const float*)d_in[1];
    const float* V      = (const float*)d_in[2];
    const float* td     = (const float*)d_in[3];
    const int*   mask   = (const int*)  d_in[4];
    const float* Wq     = (const float*)d_in[5];
    const float* Wk     = (const float*)d_in[6];
    const float* Wv     = (const float*)d_in[7];
    const float* dw_w   = (const float*)d_in[8];
    const float* pw_w   = (const float*)d_in[9];
    const float* sep_b  = (const float*)d_in[10];
    const float* ck_W   = (const float*)d_in[11];
    const float* ck_b   = (const float*)d_in[12];
    const float* co_W   = (const float*)d_in[13];
    const float* co_b   = (const float*)d_in[14];
    const float* gammas = (const float*)d_in[15];
    float* out = (float*)d_out;

    float *p_mq, *p_mk, *p_mv, *p_co, *p_mkc, *p_dwt, *p_ckp, *p_sc;
    __half* p_pr;
    cudaGetSymbolAddress((void**)&p_mq,  g_mq);
    cudaGetSymbolAddress((void**)&p_mk,  g_mk);
    cudaGetSymbolAddress((void**)&p_mv,  g_mv);
    cudaGetSymbolAddress((void**)&p_co,  g_co);
    cudaGetSymbolAddress((void**)&p_mkc, g_mkc);
    cudaGetSymbolAddress((void**)&p_dwt, g_dwt);
    cudaGetSymbolAddress((void**)&p_ckp, g_ckp);
    cudaGetSymbolAddress((void**)&p_sc,  g_sc);
    cudaGetSymbolAddress((void**)&p_pr,  g_pr);

    const int M = BB * SS;

    // order: gemm_fused is the 4th launch (ncu captures #4)
    tdsm_kernel<<<BB, 256>>>(td, mask);                                             // 1
    dw_kernel<<<dim3(HIDC / 256, SS / 16, BB), 256>>>(Kin, dw_w);                   // 2
    gemm_pw<<<dim3(M / 128, AHC / 64), 256>>>(p_dwt, pw_w, sep_b, p_mkc);           // 3
    gemm_fused<<<dim3(M / 128, AHC / 64, 4), 256>>>(Q, Kin, V, Wq, Wk, Wv,          // 4
                                                    co_W, co_b, p_mq, p_mk, p_mv, p_co);
    gemm_qk<<<dim3(SS / 128, SS / 64, BB * HH), 256>>>(p_mq, p_mk, p_sc);           // 5
    softmax_kernel<<<dim3(SS / 8, HH, BB), 256>>>(mask, gammas, p_sc, p_pr);        // 6
    gemm_pv<<<dim3(SS / 128, 1, BB * HH), 256>>>(p_pr, p_mv, out);                  // 7

    gemm_ck<<<dim3(M / 128, 1, CKZ), 256>>>(p_mkc, p_mq, ck_W, ck_b, p_ckp);        // 8
    cksm_kernel<<<(BB * SS * HH + 255) / 256, 256>>>();                             // 9
    conv_out_kernel<<<BB * SS, 128>>>(out);                                         // 10
}

// round 13
// speedup vs baseline: 1.5452x; 1.5452x over previous
#include <cuda_runtime.h>
#include <cuda_fp16.h>
#include <math.h>

#define BB   4
#define SS   1024
#define HIDC 768
#define HH   6
#define DD   64
#define AHC  384
#define KSC  9
#define PADC 4
#define OW   768   // output width = 2*AH
#define CKN  54    // H*KS
#define CKZ  6     // split-K factor for ck GEMM

typedef unsigned long long ull;

// ---------------- f32x2 packed helpers ----------------
__device__ __forceinline__ void ffma2(ull& d, ull a, ull b) {
    asm("fma.rn.f32x2 %0, %1, %2, %3;" : "=l"(d) : "l"(a), "l"(b), "l"(d));
}
__device__ __forceinline__ ull pack2(float lo, float hi) {
    ull r; asm("mov.b64 %0, {%1, %2};" : "=l"(r) : "f"(lo), "f"(hi)); return r;
}
__device__ __forceinline__ void unpack2(float& lo, float& hi, ull v) {
    asm("mov.b64 {%0, %1}, %2;" : "=f"(lo), "=f"(hi) : "l"(v));
}

// ---------------- scratch (device globals: no allocations allowed) ----------------
__device__ float g_mq [BB*SS*AHC];
__device__ float g_mk [BB*SS*AHC];
__device__ float g_mv [BB*SS*AHC];
__device__ float g_co [BB*SS*AHC];
__device__ float g_mkc[BB*SS*AHC];
__device__ float g_dwt[BB*SS*HIDC];
__device__ float g_ck [BB*SS*CKN];
__device__ float g_ckp[CKZ*BB*SS*CKN];   // split-K partials for ck logits
__device__ float g_tdsm[BB*SS];
__device__ float  g_sc [(size_t)BB*HH*SS*SS];   // scores (100 MB)
__device__ __half g_pr [(size_t)BB*HH*SS*SS];   // probs fp16 (50 MB)

// ---------------- GEMM core: C[M,N] = scale*(A@B) (+bias), 128x64 tile, f32x2 ----------------
// R9 formulation (measured best): n-paired accumulators, normal As, compact Bs,
// a-duplication via pack2 MOVs (alu pipe, dual-issues with fma pipe).
// BT=false: B is [K,N]-style row-major (row stride ldb); BT=true: C = A @ B^T.
// AHALF: A is fp16 (probs); converted during staging.
template<bool BT, bool BIAS, bool NGUARD, bool AMUL, bool AHALF>
__device__ __forceinline__ void gemm_core(const float* __restrict__ A,
                                          const float* __restrict__ A2,
                                          const float* __restrict__ Bm,
                                          const float* __restrict__ bias,
                                          float* __restrict__ C,
                                          int N, int m0, int n0,
                                          int kBeg, int kEnd,
                                          int lda, int ldb, int ldc, float scale)
{
    __shared__ float As[16][128];
    __shared__ float Bs[16][64];
    const int tid = threadIdx.x;
    const int ty = tid >> 4, tx = tid & 15;
    const int lr = tid >> 1, lk = (tid & 1) * 8;

    ull acc[8][2];
#pragma unroll
    for (int i = 0; i < 8; i++) { acc[i][0] = 0ull; acc[i][1] = 0ull; }

    for (int k0 = kBeg; k0 < kEnd; k0 += 16) {
        // ---- stage A (128 x 16) ----
        {
            float av[8];
            if (!AHALF) {
                const float* ap = A + (size_t)(m0 + lr) * lda + k0 + lk;
                float4 a0 = *(const float4*)(ap);
                float4 a1 = *(const float4*)(ap + 4);
                if (AMUL) {
                    const float* a2p = A2 + (size_t)(m0 + lr) * lda + k0 + lk;
                    float4 m0v = *(const float4*)(a2p);
                    float4 m1v = *(const float4*)(a2p + 4);
                    a0.x *= m0v.x; a0.y *= m0v.y; a0.z *= m0v.z; a0.w *= m0v.w;
                    a1.x *= m1v.x; a1.y *= m1v.y; a1.z *= m1v.z; a1.w *= m1v.w;
                }
                av[0] = a0.x; av[1] = a0.y; av[2] = a0.z; av[3] = a0.w;
                av[4] = a1.x; av[5] = a1.y; av[6] = a1.z; av[7] = a1.w;
            } else {
                const __half* ah = (const __half*)A + (size_t)(m0 + lr) * lda + k0 + lk;
                uint4 hv = *(const uint4*)ah;   // 8 halves
                float2 f0 = __half22float2(*(const __half2*)&hv.x);
                float2 f1 = __half22float2(*(const __half2*)&hv.y);
                float2 f2 = __half22float2(*(const __half2*)&hv.z);
                float2 f3 = __half22float2(*(const __half2*)&hv.w);
                av[0] = f0.x; av[1] = f0.y; av[2] = f1.x; av[3] = f1.y;
                av[4] = f2.x; av[5] = f2.y; av[6] = f3.x; av[7] = f3.y;
            }
#pragma unroll
            for (int i = 0; i < 8; i++) As[lk + i][lr] = av[i];
        }
        // ---- stage B (16 x 64) ----
        if (!BT) {
            int bk = tid >> 4, bn = (tid & 15) * 4;
            if (!NGUARD) {
                float4 bv = *(const float4*)(Bm + (size_t)(k0 + bk) * ldb + n0 + bn);
                Bs[bk][bn + 0] = bv.x; Bs[bk][bn + 1] = bv.y;
                Bs[bk][bn + 2] = bv.z; Bs[bk][bn + 3] = bv.w;
            } else {
#pragma unroll
                for (int j = 0; j < 4; j++) {
                    int n = n0 + bn + j;
                    Bs[bk][bn + j] = (n < N) ? Bm[(size_t)(k0 + bk) * ldb + n] : 0.f;
                }
            }
        } else {
            int bn = tid >> 2, bkk = (tid & 3) * 4;
            float4 bv = *(const float4*)(Bm + (size_t)(n0 + bn) * ldb + k0 + bkk);
            Bs[bkk + 0][bn] = bv.x; Bs[bkk + 1][bn] = bv.y;
            Bs[bkk + 2][bn] = bv.z; Bs[bkk + 3][bn] = bv.w;
        }
        __syncthreads();
#pragma unroll
        for (int k = 0; k < 16; k++) {
            float4 aA = *(const float4*)&As[k][ty * 8];
            float4 aB = *(const float4*)&As[k][ty * 8 + 4];
            ull b01 = *(const ull*)&Bs[k][tx * 4];
            ull b23 = *(const ull*)&Bs[k][tx * 4 + 2];
            ull ap;
            ap = pack2(aA.x, aA.x); ffma2(acc[0][0], ap, b01); ffma2(acc[0][1], ap, b23);
            ap = pack2(aA.y, aA.y); ffma2(acc[1][0], ap, b01); ffma2(acc[1][1], ap, b23);
            ap = pack2(aA.z, aA.z); ffma2(acc[2][0], ap, b01); ffma2(acc[2][1], ap, b23);
            ap = pack2(aA.w, aA.w); ffma2(acc[3][0], ap, b01); ffma2(acc[3][1], ap, b23);
            ap = pack2(aB.x, aB.x); ffma2(acc[4][0], ap, b01); ffma2(acc[4][1], ap, b23);
            ap = pack2(aB.y, aB.y); ffma2(acc[5][0], ap, b01); ffma2(acc[5][1], ap, b23);
            ap = pack2(aB.z, aB.z); ffma2(acc[6][0], ap, b01); ffma2(acc[6][1], ap, b23);
            ap = pack2(aB.w, aB.w); ffma2(acc[7][0], ap, b01); ffma2(acc[7][1], ap, b23);
        }
        __syncthreads();
    }
#pragma unroll
    for (int i = 0; i < 8; i++) {
        int m = m0 + ty * 8 + i;
#pragma unroll
        for (int p = 0; p < 2; p++) {
            float lo, hi; unpack2(lo, hi, acc[i][p]);
            int n = n0 + tx * 4 + 2 * p;
            if (!NGUARD || n < N) {
                float v = lo * scale; if (BIAS) v += bias[n];
                C[(size_t)m * ldc + n] = v;
            }
            if (!NGUARD || n + 1 < N) {
                float v = hi * scale; if (BIAS) v += bias[n + 1];
                C[(size_t)m * ldc + n + 1] = v;
            }
        }
    }
}

// fused 4-way projection GEMM: z selects (A, B, bias, C)
__global__ void __launch_bounds__(256) gemm_fused(const float* __restrict__ Q,
                                                  const float* __restrict__ Kin,
                                                  const float* __restrict__ V,
                                                  const float* __restrict__ Wq,
                                                  const float* __restrict__ Wk,
                                                  const float* __restrict__ Wv,
                                                  const float* __restrict__ coW,
                                                  const float* __restrict__ cob,
                                                  float* __restrict__ mq,
                                                  float* __restrict__ mk,
                                                  float* __restrict__ mv,
                                                  float* __restrict__ co)
{
    int m0 = blockIdx.x * 128, n0 = blockIdx.y * 64;
    switch (blockIdx.z) {
    case 0: gemm_core<false,false,false,false,false>(Q,   nullptr, Wq,  nullptr, mq, AHC, m0, n0, 0, HIDC, HIDC, AHC, AHC, 1.f); break;
    case 1: gemm_core<false,false,false,false,false>(Kin, nullptr, Wk,  nullptr, mk, AHC, m0, n0, 0, HIDC, HIDC, AHC, AHC, 1.f); break;
    case 2: gemm_core<false,false,false,false,false>(V,   nullptr, Wv,  nullptr, mv, AHC, m0, n0, 0, HIDC, HIDC, AHC, AHC, 1.f); break;
    default:gemm_core<false,true, false,false,false>(V,   nullptr, coW, cob,     co, AHC, m0, n0, 0, HIDC, HIDC, AHC, AHC, 1.f); break;
    }
}

// pointwise conv GEMM: mkc = dwt @ pw_w^T + sep_b
__global__ void __launch_bounds__(256) gemm_pw(const float* __restrict__ dwt,
                                               const float* __restrict__ pw,
                                               const float* __restrict__ sb,
                                               float* __restrict__ mkc)
{
    gemm_core<true, true, false, false, false>(dwt, nullptr, pw, sb, mkc,
                                               AHC, blockIdx.x * 128, blockIdx.y * 64,
                                               0, HIDC, HIDC, HIDC, AHC, 1.f);
}

// ck logits GEMM, split-K x CKZ
__global__ void __launch_bounds__(256) gemm_ck(const float* __restrict__ mkc,
                                               const float* __restrict__ mq,
                                               const float* __restrict__ ckW,
                                               const float* __restrict__ ckb,
                                               float* __restrict__ ckp)
{
    int z = blockIdx.z;
    const int KS_ = AHC / CKZ;   // 64
    float* Cz = ckp + (size_t)z * (BB * SS * CKN);
    if (z == 0)
        gemm_core<false, true,  true, true, false>(mkc, mq, ckW, ckb, Cz,
                                                   CKN, blockIdx.x * 128, 0, 0, KS_,
                                                   AHC, CKN, CKN, 1.f);
    else
        gemm_core<false, false, true, true, false>(mkc, mq, ckW, nullptr, Cz,
                                                   CKN, blockIdx.x * 128, 0, z * KS_, z * KS_ + KS_,
                                                   AHC, CKN, CKN, 1.f);
}

// QK GEMM: scores[b,h][i][j] = (mq_i . mk_j) / 8
__global__ void __launch_bounds__(256) gemm_qk(const float* __restrict__ mq,
                                               const float* __restrict__ mk,
                                               float* __restrict__ sc)
{
    int z = blockIdx.z;             // b*HH + h
    int b = z / HH, h = z % HH;
    const float* Aq = mq + (size_t)(b * SS) * AHC + h * DD;
    const float* Bk = mk + (size_t)(b * SS) * AHC + h * DD;
    float* Cz = sc + (size_t)z * SS * SS;
    gemm_core<true, false, false, false, false>(Aq, nullptr, Bk, nullptr, Cz,
                                                SS, blockIdx.x * 128, blockIdx.y * 64,
                                                0, DD, AHC, AHC, SS, 0.125f);
}

// PV GEMM: out[b][i][h*DD+d] = sum_j probs_fp16[i][j] * mv[j][d]
__global__ void __launch_bounds__(256) gemm_pv(const __half* __restrict__ pr,
                                               const float* __restrict__ mv,
                                               float* __restrict__ out)
{
    int z = blockIdx.z;
    int b = z / HH, h = z % HH;
    const __half* Ap = pr + (size_t)z * SS * SS;
    const float* Bv = mv + (size_t)(b * SS) * AHC + h * DD;
    float* Cz = out + (size_t)(b * SS) * OW + h * DD;
    gemm_core<false, false, false, false, true>((const float*)Ap, nullptr, Bv, nullptr, Cz,
                                                64, blockIdx.x * 128, 0,
                                                0, SS, SS, AHC, OW, 1.f);
}

// ---------------- softmax / distance-decay: fp32 scores -> fp16 probs ----------------
// grid (S/8, H, B); 8 warps x 1 row. Row staged smem-pitched (j + (j>>5)).
__global__ void __launch_bounds__(256) softmax_kernel(const int* __restrict__ mask,
                                                      const float* __restrict__ gammas,
                                                      const float* __restrict__ sc,
                                                      __half* __restrict__ pr)
{
    __shared__ float srows[8 * 1056];
    __shared__ float tdsT[1024];
    __shared__ unsigned mbits[32];

    const int tid  = threadIdx.x;
    const int w    = tid >> 5, lane = tid & 31;
    const int h    = blockIdx.y;
    const int b    = blockIdx.z;
    const int i    = blockIdx.x * 8 + w;

    for (int base = tid; base < SS; base += 256) {
        int mv = mask[b * SS + base];
        unsigned bal = __ballot_sync(0xffffffffu, mv != 0);
        if (lane == 0) mbits[base >> 5] = bal;
    }
    for (int j = tid; j < SS; j += 256)
        tdsT[((j & 31) << 5) | (j >> 5)] = g_tdsm[b * SS + j];
    __syncthreads();

    float gv = gammas[h];
    float gamma = -(gv > 20.f ? gv : log1pf(expf(gv)));   // -softplus

    float* srow = srows + w * 1056;
    const float* grow = sc + ((size_t)((b * HH + h)) * SS + i) * SS;
    __half* prow = pr + ((size_t)((b * HH + h)) * SS + i) * SS;

    // stage row: coalesced LDG.128 -> pitched smem (conflict-free)
#pragma unroll
    for (int t = 0; t < 8; t++) {
        float4 v = *(const float4*)(grow + t * 128 + lane * 4);
        int a = t * 132 + lane * 4 + (lane >> 3);
        srow[a] = v.x; srow[a + 1] = v.y; srow[a + 2] = v.z; srow[a + 3] = v.w;
    }
    __syncwarp();

    const unsigned mrow = mbits[lane];
    float sv[32];
#pragma unroll
    for (int c = 0; c < 32; c++) sv[c] = srow[lane * 33 + c];

    // pass 1: masked max
    float m1 = -3e38f;
#pragma unroll
    for (int c = 0; c < 32; c++)
        if ((mrow >> c) & 1) m1 = fmaxf(m1, sv[c]);
#pragma unroll
    for (int o = 16; o; o >>= 1) m1 = fmaxf(m1, __shfl_xor_sync(0xffffffffu, m1, o));

    // pass 2: p ~ exp * mask, inclusive cumsum
    float cuml[32];
    float run = 0.f;
#pragma unroll
    for (int c = 0; c < 32; c++) {
        float p = ((mrow >> c) & 1) ? expf(sv[c] - m1) : 0.f;
        run += p;
        cuml[c] = run;
    }
    float v = run;
#pragma unroll
    for (int o = 1; o < 32; o <<= 1) {
        float t = __shfl_up_sync(0xffffffffu, v, o);
        if (lane >= o) v += t;
    }
    float total = __shfl_sync(0xffffffffu, v, 31);
    float off = v - run;
    float invtot = 1.f / fmaxf(total, 1e-30f);

    // pass 3: total_effect, modified scores, max
    float m2 = -3e38f;
#pragma unroll
    for (int c = 0; c < 32; c++) {
        int j = lane * 32 + c;
        float s2;
        if ((mrow >> c) & 1) {
            float cum = cuml[c] + off;
            float pos = fabsf((float)(j - i));
            float rem = (total - cum) * invtot;
            float ds = sqrtf(fmaxf(rem * pos, 0.f));
            float te = expf(gamma * ds);
            te = fminf(fmaxf(te, 1e-5f), 1e5f);
            if (j < i) te -= tdsT[(c << 5) | lane];
            s2 = sv[c] * te;
        } else {
            s2 = -1e8f;
        }
        sv[c] = s2;
        m2 = fmaxf(m2, s2);
    }
#pragma unroll
    for (int o = 16; o; o >>= 1) m2 = fmaxf(m2, __shfl_xor_sync(0xffffffffu, m2, o));

    // pass 4: exp + sum, normalize, stage back
    float sum2 = 0.f;
#pragma unroll
    for (int c = 0; c < 32; c++) {
        float e = expf(sv[c] - m2);
        sv[c] = e;
        sum2 += e;
    }
#pragma unroll
    for (int o = 16; o; o >>= 1) sum2 += __shfl_xor_sync(0xffffffffu, sum2, o);
    float invs = 1.f / sum2;
#pragma unroll
    for (int c = 0; c < 32; c++) srow[lane * 33 + c] = sv[c] * invs;
    __syncwarp();

    // write back coalesced as fp16
#pragma unroll
    for (int t = 0; t < 8; t++) {
        int a = t * 132 + lane * 4 + (lane >> 3);
        __half2 h0 = __floats2half2_rn(srow[a], srow[a + 1]);
        __half2 h1 = __floats2half2_rn(srow[a + 2], srow[a + 3]);
        unsigned u0 = *(unsigned*)&h0, u1 = *(unsigned*)&h1;
        *(uint2*)(prow + t * 128 + lane * 4) = make_uint2(u0, u1);
    }
}

// ck: sum CKZ partials, softmax over KS=9, write g_ck
__global__ void __launch_bounds__(256) cksm_kernel()
{
    int row = blockIdx.x * 256 + threadIdx.x;     // BB*SS*HH rows
    if (row >= BB * SS * HH) return;
    const size_t R = (size_t)BB * SS * CKN;
    const float* p0 = g_ckp + (size_t)row * KSC;
    float v[KSC];
    float m = -3e38f;
#pragma unroll
    for (int k = 0; k < KSC; k++) {
        float s = 0.f;
#pragma unroll
        for (int z = 0; z < CKZ; z++) s += p0[z * R + k];
        v[k] = s;
        m = fmaxf(m, s);
    }
    float sum = 0.f;
#pragma unroll
    for (int k = 0; k < KSC; k++) { v[k] = expf(v[k] - m); sum += v[k]; }
    float invs = 1.f / sum;
    float* o = g_ck + (size_t)row * KSC;
#pragma unroll
    for (int k = 0; k < KSC; k++) o[k] = v[k] * invs;
}

// ---------------- depthwise conv, smem-tiled (16 s x 256 ch per block) ----------------
__global__ void __launch_bounds__(256) dw_kernel(const float* __restrict__ Kin,
                                                 const float* __restrict__ dw_w)
{
    __shared__ float smk[24][256];
    __shared__ float wsm[KSC][256];
    const int tid = threadIdx.x;
    const int c0  = blockIdx.x * 256;
    const int s0  = blockIdx.y * 16;
    const int b   = blockIdx.z;

    // stage 24 input rows (s0-4 .. s0+19), zero-padded
#pragma unroll
    for (int r = 0; r < 24; r++) {
        int sr = s0 + r - PADC;
        smk[r][tid] = (sr >= 0 && sr < SS)
            ? Kin[(size_t)(b * SS + sr) * HIDC + c0 + tid] : 0.f;
    }
    // stage weights
    for (int idx = tid; idx < 256 * KSC; idx += 256) {
        int cl = idx / KSC, k = idx % KSC;
        wsm[k][cl] = dw_w[(c0 + cl) * KSC + k];
    }
    __syncthreads();

#pragma unroll
    for (int sl = 0; sl < 16; sl++) {
        float acc = 0.f;
#pragma unroll
        for (int k = 0; k < KSC; k++)
            acc += smk[sl + k][tid] * wsm[k][tid];
        g_dwt[(size_t)(b * SS + s0 + sl) * HIDC + c0 + tid] = acc;
    }
}

// ---------------- conv_out: sliding-window gather of co weighted by ck ----------------
__global__ void __launch_bounds__(128) conv_out_kernel(float* __restrict__ out)
{
    int bs = blockIdx.x;
    int b = bs >> 10, s = bs & 1023;
    __shared__ float cks[CKN];
    if (threadIdx.x < CKN) cks[threadIdx.x] = g_ck[(size_t)bs * CKN + threadIdx.x];
    __syncthreads();
    for (int a = threadIdx.x; a < AHC; a += 128) {
        int h = a >> 6;
        float acc = 0.f;
#pragma unroll
        for (int k = 0; k < KSC; k++) {
            int sr = s + k - PADC;
            if (sr >= 0 && sr < SS)
                acc += g_co[(size_t)(b * SS + sr) * AHC + a] * cks[h * KSC + k];
        }
        out[(size_t)bs * OW + AHC + a] = acc;
    }
}

// ---------------- td softmax (independent of head and query row) ----------------
__global__ void __launch_bounds__(256) tdsm_kernel(const float* __restrict__ td,
                                                   const int* __restrict__ mask)
{
    __shared__ float red[8];
    __shared__ float bc;
    int b = blockIdx.x, tid = threadIdx.x;
    int wid = tid >> 5, ln = tid & 31;

    float ss = 0.f;
    for (int j = tid; j < SS; j += 256) { float v = td[b * SS + j]; ss += v * v; }
#pragma unroll
    for (int o = 16; o; o >>= 1) ss += __shfl_xor_sync(0xffffffffu, ss, o);
    if (ln == 0) red[wid] = ss;
    __syncthreads();
    if (tid == 0) {
        float t = 0.f;
        for (int k = 0; k < 8; k++) t += red[k];
        bc = 1.f / fmaxf(sqrtf(t), 1e-12f);
    }
    __syncthreads();
    float inv = bc;

    float m = -1e4f;
    for (int j = tid; j < SS; j += 256)
        if (mask[b * SS + j]) m = fmaxf(m, td[b * SS + j] * inv);
#pragma unroll
    for (int o = 16; o; o >>= 1) m = fmaxf(m, __shfl_xor_sync(0xffffffffu, m, o));
    if (ln == 0) red[wid] = m;
    __syncthreads();
    if (tid == 0) {
        float t = -1e4f;
        for (int k = 0; k < 8; k++) t = fmaxf(t, red[k]);
        bc = t;
    }
    __syncthreads();
    float mm = bc;
    __syncthreads();

    float den = 0.f;
    for (int j = tid; j < SS; j += 256)
        if (mask[b * SS + j]) den += expf(td[b * SS + j] * inv - mm);
#pragma unroll
    for (int o = 16; o; o >>= 1) den += __shfl_xor_sync(0xffffffffu, den, o);
    if (ln == 0) red[wid] = den;
    __syncthreads();
    if (tid == 0) {
        float t = 0.f;
        for (int k = 0; k < 8; k++) t += red[k];
        bc = 1.f / t;
    }
    __syncthreads();
    float invden = bc;

    for (int j = tid; j < SS; j += 256) {
        float v = mask[b * SS + j] ? expf(td[b * SS + j] * inv - mm) * invden : 0.f;
        g_tdsm[b * SS + j] = v;
    }
}

// ---------------- launch ----------------
extern "C" void kernel_launch(void* const* d_in, const int* in_sizes, int n_in,
                              void* d_out, int out_size)
{
    const float* Q      = (const float*)d_in[0];
    const float* Kin    = (const float*)d_in[1];
    const float* V      = (const float*)d_in[2];
    const float* td     = (const float*)d_in[3];
    const int*   mask   = (const int*)  d_in[4];
    const float* Wq     = (const float*)d_in[5];
    const float* Wk     = (const float*)d_in[6];
    const float* Wv     = (const float*)d_in[7];
    const float* dw_w   = (const float*)d_in[8];
    const float* pw_w   = (const float*)d_in[9];
    const float* sep_b  = (const float*)d_in[10];
    const float* ck_W   = (const float*)d_in[11];
    const float* ck_b   = (const float*)d_in[12];
    const float* co_W   = (const float*)d_in[13];
    const float* co_b   = (const float*)d_in[14];
    const float* gammas = (const float*)d_in[15];
    float* out = (float*)d_out;

    float *p_mq, *p_mk, *p_mv, *p_co, *p_mkc, *p_dwt, *p_ckp, *p_sc;
    __half* p_pr;
    cudaGetSymbolAddress((void**)&p_mq,  g_mq);
    cudaGetSymbolAddress((void**)&p_mk,  g_mk);
    cudaGetSymbolAddress((void**)&p_mv,  g_mv);
    cudaGetSymbolAddress((void**)&p_co,  g_co);
    cudaGetSymbolAddress((void**)&p_mkc, g_mkc);
    cudaGetSymbolAddress((void**)&p_dwt, g_dwt);
    cudaGetSymbolAddress((void**)&p_ckp, g_ckp);
    cudaGetSymbolAddress((void**)&p_sc,  g_sc);
    cudaGetSymbolAddress((void**)&p_pr,  g_pr);

    const int M = BB * SS;

    // order: gemm_fused is the 4th launch (ncu captures #4)
    tdsm_kernel<<<BB, 256>>>(td, mask);                                             // 1
    dw_kernel<<<dim3(HIDC / 256, SS / 16, BB), 256>>>(Kin, dw_w);                   // 2
    gemm_pw<<<dim3(M / 128, AHC / 64), 256>>>(p_dwt, pw_w, sep_b, p_mkc);           // 3
    gemm_fused<<<dim3(M / 128, AHC / 64, 4), 256>>>(Q, Kin, V, Wq, Wk, Wv,          // 4
                                                    co_W, co_b, p_mq, p_mk, p_mv, p_co);
    gemm_qk<<<dim3(SS / 128, SS / 64, BB * HH), 256>>>(p_mq, p_mk, p_sc);           // 5
    softmax_kernel<<<dim3(SS / 8, HH, BB), 256>>>(mask, gammas, p_sc, p_pr);        // 6
    gemm_pv<<<dim3(SS / 128, 1, BB * HH), 256>>>(p_pr, p_mv, out);                  // 7

    gemm_ck<<<dim3(M / 128, 1, CKZ), 256>>>(p_mkc, p_mq, ck_W, ck_b, p_ckp);        // 8
    cksm_kernel<<<(BB * SS * HH + 255) / 256, 256>>>();                             // 9
    conv_out_kernel<<<BB * SS, 128>>>(out);                                         // 10
}